// round 6
// baseline (speedup 1.0000x reference)
#include <cuda_runtime.h>
#include <cuda_fp16.h>
#include <cstdint>

// ---------------------------------------------------------------------------
// BigramHashEmbedding: out[t, d] = sum_h table[hash(t)][h] * proj_w[d][h]
//   hash(t) = (prev*1000003 + cur) mod 131072 (mod 2^17 -> 32-bit math ok)
//
// tcgen05 unavailable (harness targets compute_103 base, no 'a' suffix):
// warp-level mma.sync.m16n8k16 (HMMA) GEMM with cp.async pipeline.
//   prepass:  proj_w -> fp16 g_W; hash+gather table rows -> fp16 g_H
//   GEMM:     out[16384,6144] = g_H[16384,2048] @ g_W[6144,2048]^T, fp32 accum
//
// R6: same 128x128 CTA / 64x64 warp tile / 3-stage / 2 CTAs-per-SM shape as
// R5 (tensor=78%), plus:
//  - one-time clock64 spin for odd-wave CTAs to break the barrier phase-lock
//    between the two co-resident CTAs (so one CTA's sync shadow overlaps the
//    other's MMA phase),
//  - K-chunk rotation by 16 for odd-phase CTAs (order-invariant accumulation)
//    to decorrelate their LTS bursts,
//  - strided (computed) smem/gmem load offsets instead of 16-entry arrays
//    (frees ~28 registers for ptxas scheduling).
// ---------------------------------------------------------------------------

#define HID   2048
#define MODEL 6144
#define NTOK  16384

__device__ __align__(1024) __half g_W[(size_t)MODEL * HID];   // [6144, 2048]
__device__ __align__(1024) __half g_H[(size_t)NTOK  * HID];   // [16384, 2048]
__device__ int g_flag;   // 0 -> ids are int64, 1 -> ids are int32

// ------------------------------ PTX helpers -------------------------------
__device__ __forceinline__ uint32_t smem_u32(const void* p) {
    uint32_t a;
    asm("{ .reg .u64 t; cvta.to.shared.u64 t, %1; cvt.u32.u64 %0, t; }"
        : "=r"(a) : "l"(p));
    return a;
}

#define CP_ASYNC16(dst, src) \
    asm volatile("cp.async.cg.shared.global [%0], [%1], 16;" :: "r"(dst), "l"(src))
#define CP_COMMIT() asm volatile("cp.async.commit_group;" ::: "memory")
#define CP_WAIT(n)  asm volatile("cp.async.wait_group %0;" :: "n"(n) : "memory")

#define LDSM_X4(r, addr)                                                      \
    asm volatile("ldmatrix.sync.aligned.m8n8.x4.shared.b16 {%0,%1,%2,%3}, [%4];" \
        : "=r"((r)[0]), "=r"((r)[1]), "=r"((r)[2]), "=r"((r)[3]) : "r"(addr))

#define MMA16816(d, a, b0, b1)                                                \
    asm volatile("mma.sync.aligned.m16n8k16.row.col.f32.f16.f16.f32 "         \
        "{%0,%1,%2,%3}, {%4,%5,%6,%7}, {%8,%9}, {%0,%1,%2,%3};"               \
        : "+f"((d)[0]), "+f"((d)[1]), "+f"((d)[2]), "+f"((d)[3])              \
        : "r"((a)[0]), "r"((a)[1]), "r"((a)[2]), "r"((a)[3]), "r"(b0), "r"(b1))

__device__ __forceinline__ uint32_t sw128(uint32_t off) {
    return off ^ ((off >> 3) & 0x70);
}

// ------------------------------ prepass -----------------------------------
__global__ void k_convert_w(const float* __restrict__ w) {
    if (blockIdx.x == 0 && threadIdx.x == 0) g_flag = 0;  // reset dtype flag
    size_t i = (size_t)blockIdx.x * blockDim.x + threadIdx.x;  // one 16B chunk
    const float4* src = reinterpret_cast<const float4*>(w) + 2 * i;
    float4 a = src[0], b = src[1];
    __half2 h[4];
    h[0] = __floats2half2_rn(a.x, a.y);
    h[1] = __floats2half2_rn(a.z, a.w);
    h[2] = __floats2half2_rn(b.x, b.y);
    h[3] = __floats2half2_rn(b.z, b.w);
    reinterpret_cast<uint4*>(g_W)[i] = *reinterpret_cast<uint4*>(h);
}

// Probe first 8192 tokens (words 0..16383 -> in-bounds for BOTH layouts).
// If any odd 32-bit word is nonzero, the buffer cannot be int64 -> int32.
__global__ void k_detect(const unsigned* __restrict__ idw) {
    int t = blockIdx.x * blockDim.x + threadIdx.x;   // 0..8191
    if (idw[2 * t + 1] != 0) g_flag = 1;             // idempotent racy store
}

__global__ void k_gather(const void* __restrict__ ids_raw,
                         const float* __restrict__ table) {
    int t = blockIdx.x;                       // token 0..16383
    int s = t & 4095;                         // position within sequence
    unsigned cur, prev;
    if (g_flag) {                             // int32 ids
        const int* p = (const int*)ids_raw;
        cur  = (unsigned)p[t];
        prev = (s == 0) ? 0u : (unsigned)p[t - 1];
    } else {                                  // int64 ids
        const long long* p = (const long long*)ids_raw;
        cur  = (unsigned)p[t];
        prev = (s == 0) ? 0u : (unsigned)p[t - 1];
    }
    unsigned idx = (prev * 1000003u + cur) & 131071u;   // mod 2^17

    const float4* src = reinterpret_cast<const float4*>(table + (size_t)idx * HID);
    uint4* dst = reinterpret_cast<uint4*>(g_H + (size_t)t * HID);
    int i = threadIdx.x;                      // 256 threads x 8 halves = 2048
    float4 a = src[2 * i], b = src[2 * i + 1];
    __half2 h[4];
    h[0] = __floats2half2_rn(a.x, a.y);
    h[1] = __floats2half2_rn(a.z, a.w);
    h[2] = __floats2half2_rn(b.x, b.y);
    h[3] = __floats2half2_rn(b.z, b.w);
    dst[i] = *reinterpret_cast<uint4*>(h);
}

// ------------------------------- GEMM --------------------------------------
// CTA 128x128, 128 threads (4 warps, 2m x 2n, warp tile 64x64), BK=64 halves
// (128B rows, SW128-style xor swizzle). 3-stage cp.async pipeline.
// 96KB smem/CTA -> 2 CTAs/SM so barrier shadows overlap across CTAs.
static constexpr int BM = 128, BN = 128, BK = 64, S = 3;
static constexpr int KT = HID / BK;                 // 32
static constexpr int A_BYTES = BM * 128;            // 16384
static constexpr int B_BYTES = BN * 128;            // 16384
static constexpr int STAGE   = A_BYTES + B_BYTES;   // 32768
static constexpr int SMEM_TOTAL = S * STAGE + 1024; // 99328 (incl. align pad)

// Load one K-chunk c into stage base `sbase`. Offsets are affine in q:
// smem +2048 per q (swizzle unaffected: +16 rows keeps row%8), gmem +16 rows.
#define LOAD_STAGE(sbase, c) do {                                             \
    uint32_t _kb = (uint32_t)(c) * 128u;                                      \
    _Pragma("unroll")                                                         \
    for (int q = 0; q < 8; q++)                                               \
        CP_ASYNC16((sbase) + s0 + q * 2048u, pA + (size_t)q * 65536 + _kb);   \
    _Pragma("unroll")                                                         \
    for (int q = 0; q < 8; q++)                                               \
        CP_ASYNC16((sbase) + (uint32_t)A_BYTES + s0 + q * 2048u,              \
                   pB + (size_t)q * 65536 + _kb);                             \
} while (0)

__global__ void __launch_bounds__(128, 2) k_gemm(float* __restrict__ out) {
    extern __shared__ char smem[];
    uint32_t sb = (smem_u32(smem) + 1023) & ~1023u;

    int tid  = threadIdx.x;
    int lane = tid & 31;
    int wid  = tid >> 5;

    int n0 = blockIdx.x * BN;   // model-dim tile (fast dim -> weights hot in L2)
    int m0 = blockIdx.y * BM;   // token tile

    // Phase: co-resident CTA pairs are wave-adjacent (bid and bid+148) ->
    // opposite phases. Odd phase: one-time spin to break barrier lockstep,
    // plus K-chunk rotation by 16 to decorrelate LTS bursts.
    int bid   = blockIdx.y * gridDim.x + blockIdx.x;
    int phase = (bid / 148) & 1;
    int koff  = phase << 4;
    if (phase) {
        long long t0 = clock64();
        while (clock64() - t0 < 1200) { }
    }

    int m0w = (wid & 1) * 64;   // warp tile origin within CTA
    int n0w = (wid >> 1) * 64;

    // --- per-lane ldmatrix address terms (swizzle: xor (row%8)*16) ---
    uint32_t a_row[4], a_xor[4];
    #pragma unroll
    for (int i = 0; i < 4; i++) {
        int r = m0w + i * 16 + (lane & 15);
        a_row[i] = (uint32_t)r * 128u;
        a_xor[i] = (uint32_t)(r & 7) * 16u;
    }
    uint32_t a_kadd = (uint32_t)(lane >> 4) * 16u;

    uint32_t b_row[4], b_xor[4];
    #pragma unroll
    for (int h = 0; h < 4; h++) {
        int r = n0w + 16 * h + (lane & 7) + ((lane >> 4) & 1) * 8;
        b_row[h] = (uint32_t)r * 128u;
        b_xor[h] = (uint32_t)(r & 7) * 16u;
    }
    uint32_t b_kadd = (uint32_t)((lane >> 3) & 1) * 16u;

    // --- strided global->shared load plan (replaces 16-entry arrays) ---
    uint32_t s0 = sw128(((uint32_t)(tid >> 3) * 128u) | ((uint32_t)(tid & 7) * 16u));
    const char* pA = (const char*)g_H +
                     ((size_t)(m0 + (tid >> 3)) * HID + (size_t)(tid & 7) * 8) * 2;
    const char* pB = (const char*)g_W +
                     ((size_t)(n0 + (tid >> 3)) * HID + (size_t)(tid & 7) * 8) * 2;

    // --- prologue: fill S-1 stages ---
    #pragma unroll
    for (int s = 0; s < S - 1; s++) {
        LOAD_STAGE(sb + s * STAGE, (s + koff) & (KT - 1));
        CP_COMMIT();
    }

    float acc[4][8][4];
    #pragma unroll
    for (int i = 0; i < 4; i++)
        #pragma unroll
        for (int j = 0; j < 8; j++)
            #pragma unroll
            for (int v = 0; v < 4; v++) acc[i][j][v] = 0.f;

    // --- mainloop ---
    int slot = 0, lslot = S - 1;
    for (int kt = 0; kt < KT; ++kt) {
        CP_WAIT(S - 2);        // chunk kt's group complete
        __syncthreads();       // all warps done with slot being overwritten

        int ld = kt + S - 1;
        if (ld < KT) LOAD_STAGE(sb + lslot * STAGE, (ld + koff) & (KT - 1));
        CP_COMMIT();           // commit every iteration (empty at tail)

        uint32_t Ab = sb + slot * STAGE;
        uint32_t Bb = Ab + A_BYTES;
        if (++slot == S)  slot = 0;
        if (++lslot == S) lslot = 0;

        #pragma unroll
        for (int kk = 0; kk < 4; kk++) {
            uint32_t kb = (uint32_t)kk * 32u;
            uint32_t a[4][4];
            #pragma unroll
            for (int i = 0; i < 4; i++)
                LDSM_X4(a[i], Ab + a_row[i] + ((kb + a_kadd) ^ a_xor[i]));
            uint32_t b[4][4];
            #pragma unroll
            for (int h = 0; h < 4; h++)
                LDSM_X4(b[h], Bb + b_row[h] + ((kb + b_kadd) ^ b_xor[h]));
            #pragma unroll
            for (int i = 0; i < 4; i++)
                #pragma unroll
                for (int j = 0; j < 8; j++)
                    MMA16816(acc[i][j], a[i], b[j >> 1][(j & 1) * 2],
                             b[j >> 1][(j & 1) * 2 + 1]);
        }
    }

    // --- epilogue: direct fp32 stores ---
    int g  = lane >> 2;
    int tc = lane & 3;
    #pragma unroll
    for (int i = 0; i < 4; i++) {
        size_t r = (size_t)(m0 + m0w + i * 16 + g);
        float* rp = out + r * MODEL + n0 + n0w + 2 * tc;
        #pragma unroll
        for (int j = 0; j < 8; j++) {
            float2 lo = make_float2(acc[i][j][0], acc[i][j][1]);
            float2 hi = make_float2(acc[i][j][2], acc[i][j][3]);
            *reinterpret_cast<float2*>(rp + j * 8)              = lo;
            *reinterpret_cast<float2*>(rp + j * 8 + 8 * MODEL)  = hi;
        }
    }
}

// ------------------------------ launcher -----------------------------------
extern "C" void kernel_launch(void* const* d_in, const int* in_sizes, int n_in,
                              void* d_out, int out_size) {
    const void*  ids   = d_in[0];                 // int32 or int64 [4,4096]
    const float* table = (const float*)d_in[1];   // [131072, 2048]
    const float* projw = (const float*)d_in[2];   // [6144, 2048]
    float* out = (float*)d_out;                   // [4,4096,6144]

    k_convert_w<<<(MODEL * HID / 8) / 256, 256>>>(projw);
    k_detect<<<8192 / 256, 256>>>((const unsigned*)ids);
    k_gather<<<NTOK, 256>>>(ids, table);

    cudaFuncSetAttribute(k_gemm, cudaFuncAttributeMaxDynamicSharedMemorySize, SMEM_TOTAL);
    dim3 grid(MODEL / BN, NTOK / BM);   // (48, 128), n-tile fast
    k_gemm<<<grid, 128, SMEM_TOTAL>>>(out);
}

// round 7
// speedup vs baseline: 1.0301x; 1.0301x over previous
#include <cuda_runtime.h>
#include <cuda_fp16.h>
#include <cstdint>

// ---------------------------------------------------------------------------
// BigramHashEmbedding: out[t, d] = sum_h table[hash(t)][h] * proj_w[d][h]
//   hash(t) = (prev*1000003 + cur) mod 131072 (mod 2^17 -> 32-bit math ok)
//
// tcgen05 unavailable (harness targets compute_103 base, no 'a' suffix):
// warp-level mma.sync.m16n8k16 (HMMA) GEMM with cp.async pipeline.
//   prepass:  proj_w -> fp16 g_W; hash+gather table rows -> fp16 g_H
//   GEMM:     out[16384,6144] = g_H[16384,2048] @ g_W[6144,2048]^T, fp32 accum
//
// R7: the limiter is warps/SMSP, not barriers (R6 falsified the phase-lock
// theory). Per-warp LDSM->MMA duty is ~60%; 2 warps/SMSP gave 78% tensor.
// Shrink warp tile to 64x32 (64 acc regs) and CTA to 128x64 / 4 warps with
// 24KB stages (S=3, 73.7KB/CTA) -> 3 CTAs/SM -> 3 warps/SMSP oversubscribe
// the tensor pipe. Fill traffic rises (A re-read 96x) but L2/L1 have slack.
// ---------------------------------------------------------------------------

#define HID   2048
#define MODEL 6144
#define NTOK  16384

__device__ __align__(1024) __half g_W[(size_t)MODEL * HID];   // [6144, 2048]
__device__ __align__(1024) __half g_H[(size_t)NTOK  * HID];   // [16384, 2048]
__device__ int g_flag;   // 0 -> ids are int64, 1 -> ids are int32

// ------------------------------ PTX helpers -------------------------------
__device__ __forceinline__ uint32_t smem_u32(const void* p) {
    uint32_t a;
    asm("{ .reg .u64 t; cvta.to.shared.u64 t, %1; cvt.u32.u64 %0, t; }"
        : "=r"(a) : "l"(p));
    return a;
}

#define CP_ASYNC16(dst, src) \
    asm volatile("cp.async.cg.shared.global [%0], [%1], 16;" :: "r"(dst), "l"(src))
#define CP_COMMIT() asm volatile("cp.async.commit_group;" ::: "memory")
#define CP_WAIT(n)  asm volatile("cp.async.wait_group %0;" :: "n"(n) : "memory")

#define LDSM_X4(r, addr)                                                      \
    asm volatile("ldmatrix.sync.aligned.m8n8.x4.shared.b16 {%0,%1,%2,%3}, [%4];" \
        : "=r"((r)[0]), "=r"((r)[1]), "=r"((r)[2]), "=r"((r)[3]) : "r"(addr))

#define MMA16816(d, a, b0, b1)                                                \
    asm volatile("mma.sync.aligned.m16n8k16.row.col.f32.f16.f16.f32 "         \
        "{%0,%1,%2,%3}, {%4,%5,%6,%7}, {%8,%9}, {%0,%1,%2,%3};"               \
        : "+f"((d)[0]), "+f"((d)[1]), "+f"((d)[2]), "+f"((d)[3])              \
        : "r"((a)[0]), "r"((a)[1]), "r"((a)[2]), "r"((a)[3]), "r"(b0), "r"(b1))

__device__ __forceinline__ uint32_t sw128(uint32_t off) {
    return off ^ ((off >> 3) & 0x70);
}

// ------------------------------ prepass -----------------------------------
__global__ void k_convert_w(const float* __restrict__ w) {
    if (blockIdx.x == 0 && threadIdx.x == 0) g_flag = 0;  // reset dtype flag
    size_t i = (size_t)blockIdx.x * blockDim.x + threadIdx.x;  // one 16B chunk
    const float4* src = reinterpret_cast<const float4*>(w) + 2 * i;
    float4 a = src[0], b = src[1];
    __half2 h[4];
    h[0] = __floats2half2_rn(a.x, a.y);
    h[1] = __floats2half2_rn(a.z, a.w);
    h[2] = __floats2half2_rn(b.x, b.y);
    h[3] = __floats2half2_rn(b.z, b.w);
    reinterpret_cast<uint4*>(g_W)[i] = *reinterpret_cast<uint4*>(h);
}

// Probe first 8192 tokens (words 0..16383 -> in-bounds for BOTH layouts).
// If any odd 32-bit word is nonzero, the buffer cannot be int64 -> int32.
__global__ void k_detect(const unsigned* __restrict__ idw) {
    int t = blockIdx.x * blockDim.x + threadIdx.x;   // 0..8191
    if (idw[2 * t + 1] != 0) g_flag = 1;             // idempotent racy store
}

__global__ void k_gather(const void* __restrict__ ids_raw,
                         const float* __restrict__ table) {
    int t = blockIdx.x;                       // token 0..16383
    int s = t & 4095;                         // position within sequence
    unsigned cur, prev;
    if (g_flag) {                             // int32 ids
        const int* p = (const int*)ids_raw;
        cur  = (unsigned)p[t];
        prev = (s == 0) ? 0u : (unsigned)p[t - 1];
    } else {                                  // int64 ids
        const long long* p = (const long long*)ids_raw;
        cur  = (unsigned)p[t];
        prev = (s == 0) ? 0u : (unsigned)p[t - 1];
    }
    unsigned idx = (prev * 1000003u + cur) & 131071u;   // mod 2^17

    const float4* src = reinterpret_cast<const float4*>(table + (size_t)idx * HID);
    uint4* dst = reinterpret_cast<uint4*>(g_H + (size_t)t * HID);
    int i = threadIdx.x;                      // 256 threads x 8 halves = 2048
    float4 a = src[2 * i], b = src[2 * i + 1];
    __half2 h[4];
    h[0] = __floats2half2_rn(a.x, a.y);
    h[1] = __floats2half2_rn(a.z, a.w);
    h[2] = __floats2half2_rn(b.x, b.y);
    h[3] = __floats2half2_rn(b.z, b.w);
    dst[i] = *reinterpret_cast<uint4*>(h);
}

// ------------------------------- GEMM --------------------------------------
// CTA 128x64, 128 threads (4 warps, 2m x 2n, warp tile 64x32), BK=64 halves
// (128B rows, SW128-style xor swizzle). 3-stage cp.async pipeline.
// 73.7KB smem/CTA -> 3 CTAs/SM -> 3 warps/SMSP.
static constexpr int BM = 128, BN = 64, BK = 64, S = 3;
static constexpr int KT = HID / BK;                 // 32
static constexpr int A_BYTES = BM * 128;            // 16384
static constexpr int B_BYTES = BN * 128;            // 8192
static constexpr int STAGE   = A_BYTES + B_BYTES;   // 24576
static constexpr int SMEM_TOTAL = S * STAGE + 1024; // 74752 (incl. align pad)

// Load one K-chunk c into stage base `sbase`. Offsets affine in q:
// smem +2048 per q (+16 rows, swizzle-safe), gmem +16 rows (= +65536 bytes).
#define LOAD_STAGE(sbase, c) do {                                             \
    uint32_t _kb = (uint32_t)(c) * 128u;                                      \
    _Pragma("unroll")                                                         \
    for (int q = 0; q < 8; q++)                                               \
        CP_ASYNC16((sbase) + s0 + q * 2048u, pA + (size_t)q * 65536 + _kb);   \
    _Pragma("unroll")                                                         \
    for (int q = 0; q < 4; q++)                                               \
        CP_ASYNC16((sbase) + (uint32_t)A_BYTES + s0 + q * 2048u,              \
                   pB + (size_t)q * 65536 + _kb);                             \
} while (0)

__global__ void __launch_bounds__(128, 3) k_gemm(float* __restrict__ out) {
    extern __shared__ char smem[];
    uint32_t sb = (smem_u32(smem) + 1023) & ~1023u;

    int tid  = threadIdx.x;
    int lane = tid & 31;
    int wid  = tid >> 5;

    int n0 = blockIdx.x * BN;   // model-dim tile (fast dim -> weights hot in L2)
    int m0 = blockIdx.y * BM;   // token tile
    int m0w = (wid & 1) * 64;   // warp tile origin within CTA
    int n0w = (wid >> 1) * 32;

    // --- per-lane ldmatrix address terms (swizzle: xor (row%8)*16) ---
    uint32_t a_row[4], a_xor[4];
    #pragma unroll
    for (int i = 0; i < 4; i++) {
        int r = m0w + i * 16 + (lane & 15);
        a_row[i] = (uint32_t)r * 128u;
        a_xor[i] = (uint32_t)(r & 7) * 16u;
    }
    uint32_t a_kadd = (uint32_t)(lane >> 4) * 16u;

    uint32_t b_row[2], b_xor[2];
    #pragma unroll
    for (int h = 0; h < 2; h++) {
        int r = n0w + 16 * h + (lane & 7) + ((lane >> 4) & 1) * 8;
        b_row[h] = (uint32_t)r * 128u;
        b_xor[h] = (uint32_t)(r & 7) * 16u;
    }
    uint32_t b_kadd = (uint32_t)((lane >> 3) & 1) * 16u;

    // --- strided global->shared load plan ---
    uint32_t s0 = sw128(((uint32_t)(tid >> 3) * 128u) | ((uint32_t)(tid & 7) * 16u));
    const char* pA = (const char*)g_H +
                     ((size_t)(m0 + (tid >> 3)) * HID + (size_t)(tid & 7) * 8) * 2;
    const char* pB = (const char*)g_W +
                     ((size_t)(n0 + (tid >> 3)) * HID + (size_t)(tid & 7) * 8) * 2;

    // --- prologue: fill S-1 stages ---
    #pragma unroll
    for (int s = 0; s < S - 1; s++) {
        LOAD_STAGE(sb + s * STAGE, s);
        CP_COMMIT();
    }

    float acc[4][4][4];
    #pragma unroll
    for (int i = 0; i < 4; i++)
        #pragma unroll
        for (int j = 0; j < 4; j++)
            #pragma unroll
            for (int v = 0; v < 4; v++) acc[i][j][v] = 0.f;

    // --- mainloop ---
    int slot = 0, lslot = S - 1;
    for (int kt = 0; kt < KT; ++kt) {
        CP_WAIT(S - 2);        // chunk kt's group complete
        __syncthreads();       // all warps done with slot being overwritten

        int ld = kt + S - 1;
        if (ld < KT) LOAD_STAGE(sb + lslot * STAGE, ld);
        CP_COMMIT();           // commit every iteration (empty at tail)

        uint32_t Ab = sb + slot * STAGE;
        uint32_t Bb = Ab + A_BYTES;
        if (++slot == S)  slot = 0;
        if (++lslot == S) lslot = 0;

        #pragma unroll
        for (int kk = 0; kk < 4; kk++) {
            uint32_t kb = (uint32_t)kk * 32u;
            uint32_t a[4][4];
            #pragma unroll
            for (int i = 0; i < 4; i++)
                LDSM_X4(a[i], Ab + a_row[i] + ((kb + a_kadd) ^ a_xor[i]));
            uint32_t b[2][4];
            #pragma unroll
            for (int h = 0; h < 2; h++)
                LDSM_X4(b[h], Bb + b_row[h] + ((kb + b_kadd) ^ b_xor[h]));
            #pragma unroll
            for (int i = 0; i < 4; i++)
                #pragma unroll
                for (int j = 0; j < 4; j++)
                    MMA16816(acc[i][j], a[i], b[j >> 1][(j & 1) * 2],
                             b[j >> 1][(j & 1) * 2 + 1]);
        }
    }

    // --- epilogue: direct fp32 stores ---
    int g  = lane >> 2;
    int tc = lane & 3;
    #pragma unroll
    for (int i = 0; i < 4; i++) {
        size_t r = (size_t)(m0 + m0w + i * 16 + g);
        float* rp = out + r * MODEL + n0 + n0w + 2 * tc;
        #pragma unroll
        for (int j = 0; j < 4; j++) {
            float2 lo = make_float2(acc[i][j][0], acc[i][j][1]);
            float2 hi = make_float2(acc[i][j][2], acc[i][j][3]);
            *reinterpret_cast<float2*>(rp + j * 8)              = lo;
            *reinterpret_cast<float2*>(rp + j * 8 + 8 * MODEL)  = hi;
        }
    }
}

// ------------------------------ launcher -----------------------------------
extern "C" void kernel_launch(void* const* d_in, const int* in_sizes, int n_in,
                              void* d_out, int out_size) {
    const void*  ids   = d_in[0];                 // int32 or int64 [4,4096]
    const float* table = (const float*)d_in[1];   // [131072, 2048]
    const float* projw = (const float*)d_in[2];   // [6144, 2048]
    float* out = (float*)d_out;                   // [4,4096,6144]

    k_convert_w<<<(MODEL * HID / 8) / 256, 256>>>(projw);
    k_detect<<<8192 / 256, 256>>>((const unsigned*)ids);
    k_gather<<<NTOK, 256>>>(ids, table);

    cudaFuncSetAttribute(k_gemm, cudaFuncAttributeMaxDynamicSharedMemorySize, SMEM_TOTAL);
    dim3 grid(MODEL / BN, NTOK / BM);   // (96, 128), n-tile fast
    k_gemm<<<grid, 128, SMEM_TOTAL>>>(out);
}